// round 2
// baseline (speedup 1.0000x reference)
#include <cuda_runtime.h>
#include <math.h>

#define MS 4096            // square: M == N == 4096
#define RD 16
#define NP 136             // 16*17/2 symmetric pairs
#define SPL 8              // split-K factor for col-mode
#define TS 512             // samples per split / smem tile
#define EPSR 1e-5f

// ---------------- scratch: ~25 MB total of device globals ----------------
__device__ float g_Apart[(size_t)SPL * NP * MS];   // 17.8 MB col-mode Gram partials
__device__ float g_A[(size_t)MS * NP];             //  2.2 MB row-mode Gram (direct)
__device__ float g_Ainv[(size_t)MS * RD * RD];     //  4.0 MB
__device__ float g_U[MS * RD];
__device__ float g_Vt[MS * RD];                    // V stored transposed: [n][r]
__device__ float g_t[MS * RD];
__device__ float g_tpart[(size_t)SPL * MS * RD];   //  2.0 MB
__device__ float g_ssq[MS];
__device__ float g_ssqpart[SPL * MS];
__device__ float g_cntpart[SPL * MS];
__device__ float g_cntc[MS];
__device__ float g_cntr[MS];
__device__ float g_sig[MS];
__device__ float g_coef[4];                        // c, lamda, mu, alpha

// ---------------- setup: copy U, transpose V ----------------
__global__ void k_setup(const float* __restrict__ U, const float* __restrict__ V) {
    int tid = blockIdx.x * 256 + threadIdx.x;      // 65536
    g_U[tid] = U[tid];
    int n = tid >> 4, r = tid & 15;
    g_Vt[tid] = V[r * MS + n];
}

// ---------------- counts ----------------
__global__ void k_cnt_col(const float* __restrict__ X) {
    int j = blockIdx.x * 256 + threadIdx.x;
    int s0 = blockIdx.y * TS;
    float c = 0.f;
    for (int s = 0; s < TS; s++)
        c += (X[(size_t)(s0 + s) * MS + j] != 0.f) ? 1.f : 0.f;
    g_cntpart[blockIdx.y * MS + j] = c;
}
__global__ void k_cnt_fin() {
    int j = blockIdx.x * 256 + threadIdx.x;
    float c = 0.f;
    #pragma unroll
    for (int sp = 0; sp < SPL; sp++) c += g_cntpart[sp * MS + j];
    g_cntc[j] = c;
}
__global__ void k_cnt_row(const float* __restrict__ X) {
    int wid = threadIdx.x >> 5, lane = threadIdx.x & 31;
    int i = blockIdx.x * 8 + wid;
    float c = 0.f;
    for (int s = lane; s < MS; s += 32)
        c += (X[(size_t)i * MS + s] != 0.f) ? 1.f : 0.f;
    #pragma unroll
    for (int off = 16; off; off >>= 1) c += __shfl_xor_sync(~0u, c, off);
    if (lane == 0) g_cntr[i] = c;
}

// ---------------- per-layer coefficients (closed-form chi2 cdfs) ----------------
__global__ void k_coef(const float* __restrict__ c, const float* __restrict__ lam,
                       const float* __restrict__ mu, int layer) {
    if (threadIdx.x == 0) {
        double cl = (double)c[layer];
        double chi1 = erf(sqrt(cl));                       // chi2.cdf(2c,1)
        double y = 0.5 * cl * cl;                          // chi2.cdf(c^2,3):
        double chi3 = erf(sqrt(y)) - 2.0 * sqrt(y) * exp(-y) / sqrt(3.14159265358979323846);
        double alpha = cl * (1.0 - chi1) + 0.5 * chi3;
        g_coef[0] = (float)cl;
        g_coef[1] = lam[layer];
        g_coef[2] = mu[layer];
        g_coef[3] = (float)alpha;
    }
}

// ================= col-mode (items = columns of X, F = U, B = Vt) =================
__global__ __launch_bounds__(256, 1) void k_A_col(const float* __restrict__ X) {
    __shared__ float sF[TS * RD];
    int tx = threadIdx.x;
    int j = blockIdx.x * 256 + tx;
    int s0 = blockIdx.y * TS;
    #pragma unroll
    for (int k = 0; k < 32; k++)
        sF[tx + k * 256] = g_U[s0 * RD + tx + k * 256];
    __syncthreads();

    float acc[NP];
    #pragma unroll
    for (int p = 0; p < NP; p++) acc[p] = 0.f;

    for (int s = 0; s < TS; s++) {
        float d = X[(size_t)(s0 + s) * MS + j];
        float w = (d != 0.f) ? 1.f : 0.f;
        float u[RD];
        #pragma unroll
        for (int r = 0; r < RD; r++) u[r] = w * sF[s * RD + r];
        #pragma unroll
        for (int r = 0; r < RD; r++)
            #pragma unroll
            for (int cc = 0; cc <= r; cc++)
                acc[r * (r + 1) / 2 + cc] += u[r] * u[cc];
    }
    #pragma unroll
    for (int p = 0; p < NP; p++)
        g_Apart[((size_t)blockIdx.y * NP + p) * MS + j] = acc[p];
}

__global__ __launch_bounds__(256) void k_res_col(const float* __restrict__ X) {
    __shared__ float sF[TS * RD];
    int tx = threadIdx.x;
    int j = blockIdx.x * 256 + tx;
    int s0 = blockIdx.y * TS;
    #pragma unroll
    for (int k = 0; k < 32; k++)
        sF[tx + k * 256] = g_U[s0 * RD + tx + k * 256];
    float b[RD];
    #pragma unroll
    for (int r = 0; r < RD; r++) b[r] = g_Vt[j * RD + r];
    float cl = g_coef[0];
    float inv_sig = 1.f / g_sig[j];
    __syncthreads();

    float acc = 0.f;
    for (int s = 0; s < TS; s++) {
        float d = X[(size_t)(s0 + s) * MS + j];
        float dot = 0.f;
        #pragma unroll
        for (int r = 0; r < RD; r++) dot += sF[s * RD + r] * b[r];
        float rv = (d != 0.f) ? (d - dot) : 0.f;
        float ps = fminf(fmaxf(rv * inv_sig, -cl), cl);
        acc += ps * ps;
    }
    g_ssqpart[blockIdx.y * MS + j] = acc;
}

__global__ __launch_bounds__(256) void k_t_col(const float* __restrict__ X) {
    __shared__ float sF[TS * RD];
    int tx = threadIdx.x;
    int j = blockIdx.x * 256 + tx;
    int s0 = blockIdx.y * TS;
    #pragma unroll
    for (int k = 0; k < 32; k++)
        sF[tx + k * 256] = g_U[s0 * RD + tx + k * 256];
    float b[RD];
    #pragma unroll
    for (int r = 0; r < RD; r++) b[r] = g_Vt[j * RD + r];
    float thr = g_coef[0] * g_sig[j];
    __syncthreads();

    float acc[RD];
    #pragma unroll
    for (int r = 0; r < RD; r++) acc[r] = 0.f;
    for (int s = 0; s < TS; s++) {
        float d = X[(size_t)(s0 + s) * MS + j];
        float dot = 0.f;
        #pragma unroll
        for (int r = 0; r < RD; r++) dot += sF[s * RD + r] * b[r];
        float rv = (d != 0.f) ? (d - dot) : 0.f;
        float pc = fminf(fmaxf(rv, -thr), thr);
        #pragma unroll
        for (int r = 0; r < RD; r++) acc[r] += sF[s * RD + r] * pc;
    }
    #pragma unroll
    for (int r = 0; r < RD; r++)
        g_tpart[((size_t)blockIdx.y * MS + j) * RD + r] = acc[r];
}

__global__ void k_redt() {
    int tid = blockIdx.x * 256 + threadIdx.x;      // 65536
    int i = tid >> 4, r = tid & 15;
    float s = 0.f;
    #pragma unroll
    for (int sp = 0; sp < SPL; sp++)
        s += g_tpart[((size_t)sp * MS + i) * RD + r];
    g_t[tid] = s;
}

// ================= row-mode (items = rows of X, F = V cols, B = U) =================
__global__ __launch_bounds__(256, 1) void k_A_row(const float* __restrict__ X) {
    __shared__ float sV[RD * 513];
    int tx = threadIdx.x, wid = tx >> 5, lane = tx & 31;
    int i = blockIdx.x * 8 + wid;

    float acc[NP];
    #pragma unroll
    for (int p = 0; p < NP; p++) acc[p] = 0.f;

    for (int t = 0; t < 8; t++) {
        __syncthreads();
        #pragma unroll
        for (int k = 0; k < 32; k++) {
            int idx = tx + k * 256;                // 0..8191
            int s = idx >> 4, r = idx & 15;
            sV[r * 513 + s] = g_Vt[t * 8192 + idx];
        }
        __syncthreads();
        #pragma unroll 2
        for (int k = 0; k < 16; k++) {
            int s = lane + k * 32;
            float d = X[(size_t)i * MS + t * TS + s];
            float w = (d != 0.f) ? 1.f : 0.f;
            float v[RD];
            #pragma unroll
            for (int r = 0; r < RD; r++) v[r] = w * sV[r * 513 + s];
            #pragma unroll
            for (int r = 0; r < RD; r++)
                #pragma unroll
                for (int cc = 0; cc <= r; cc++)
                    acc[r * (r + 1) / 2 + cc] += v[r] * v[cc];
        }
    }
    #pragma unroll
    for (int p = 0; p < NP; p++) {
        #pragma unroll
        for (int off = 16; off; off >>= 1)
            acc[p] += __shfl_xor_sync(~0u, acc[p], off);
    }
    if (lane == 0) {
        #pragma unroll
        for (int p = 0; p < NP; p++) g_A[(size_t)i * NP + p] = acc[p];
    }
}

__global__ __launch_bounds__(256) void k_res_row(const float* __restrict__ X) {
    __shared__ float sV[RD * 513];
    int tx = threadIdx.x, wid = tx >> 5, lane = tx & 31;
    int i = blockIdx.x * 8 + wid;
    float b[RD];
    #pragma unroll
    for (int r = 0; r < RD; r++) b[r] = g_U[i * RD + r];
    float cl = g_coef[0];
    float inv_sig = 1.f / g_sig[i];

    float acc = 0.f;
    for (int t = 0; t < 8; t++) {
        __syncthreads();
        #pragma unroll
        for (int k = 0; k < 32; k++) {
            int idx = tx + k * 256;
            int s = idx >> 4, r = idx & 15;
            sV[r * 513 + s] = g_Vt[t * 8192 + idx];
        }
        __syncthreads();
        #pragma unroll 2
        for (int k = 0; k < 16; k++) {
            int s = lane + k * 32;
            float d = X[(size_t)i * MS + t * TS + s];
            float dot = 0.f;
            #pragma unroll
            for (int r = 0; r < RD; r++) dot += sV[r * 513 + s] * b[r];
            float rv = (d != 0.f) ? (d - dot) : 0.f;
            float ps = fminf(fmaxf(rv * inv_sig, -cl), cl);
            acc += ps * ps;
        }
    }
    #pragma unroll
    for (int off = 16; off; off >>= 1) acc += __shfl_xor_sync(~0u, acc, off);
    if (lane == 0) g_ssq[i] = acc;
}

__global__ __launch_bounds__(256) void k_t_row(const float* __restrict__ X) {
    __shared__ float sV[RD * 513];
    int tx = threadIdx.x, wid = tx >> 5, lane = tx & 31;
    int i = blockIdx.x * 8 + wid;
    float b[RD];
    #pragma unroll
    for (int r = 0; r < RD; r++) b[r] = g_U[i * RD + r];
    float thr = g_coef[0] * g_sig[i];

    float acc[RD];
    #pragma unroll
    for (int r = 0; r < RD; r++) acc[r] = 0.f;
    for (int t = 0; t < 8; t++) {
        __syncthreads();
        #pragma unroll
        for (int k = 0; k < 32; k++) {
            int idx = tx + k * 256;
            int s = idx >> 4, r = idx & 15;
            sV[r * 513 + s] = g_Vt[t * 8192 + idx];
        }
        __syncthreads();
        #pragma unroll 2
        for (int k = 0; k < 16; k++) {
            int s = lane + k * 32;
            float d = X[(size_t)i * MS + t * TS + s];
            float dot = 0.f;
            #pragma unroll
            for (int r = 0; r < RD; r++) dot += sV[r * 513 + s] * b[r];
            float rv = (d != 0.f) ? (d - dot) : 0.f;
            float pc = fminf(fmaxf(rv, -thr), thr);
            #pragma unroll
            for (int r = 0; r < RD; r++) acc[r] += sV[r * 513 + s] * pc;
        }
    }
    #pragma unroll
    for (int r = 0; r < RD; r++) {
        #pragma unroll
        for (int off = 16; off; off >>= 1)
            acc[r] += __shfl_xor_sync(~0u, acc[r], off);
    }
    if (lane == 0) {
        #pragma unroll
        for (int r = 0; r < RD; r++) g_t[i * RD + r] = acc[r];
    }
}

// ---------------- reduce + ridge + invert 16x16 (Gauss-Jordan) ----------------
__global__ void k_inv(int mode) {
    __shared__ float Mm[16][33];
    int t = threadIdx.x;
    int r = t >> 4, cc = t & 15;
    int i = blockIdx.x;

    int rr = max(r, cc), cs = min(r, cc);
    int p = rr * (rr + 1) / 2 + cs;
    float sum;
    if (mode == 0) {
        sum = 0.f;
        #pragma unroll
        for (int sp = 0; sp < SPL; sp++)
            sum += g_Apart[((size_t)sp * NP + p) * MS + i];
    } else {
        sum = g_A[(size_t)i * NP + p];
    }
    if (r == cc) sum += EPSR;
    Mm[r][cc] = sum;
    Mm[r][cc + 16] = (r == cc) ? 1.f : 0.f;
    __syncthreads();

    for (int k = 0; k < 16; k++) {
        float piv = Mm[k][k];
        __syncthreads();
        if (r == k) {
            float pivinv = 1.f / piv;
            Mm[k][cc] *= pivinv;
            Mm[k][cc + 16] *= pivinv;
        }
        __syncthreads();
        float f = Mm[r][k];
        float mk1 = Mm[k][cc];
        float mk2 = Mm[k][cc + 16];
        __syncthreads();
        if (r != k) {
            Mm[r][cc] -= f * mk1;
            Mm[r][cc + 16] -= f * mk2;
        }
        __syncthreads();
    }
    g_Ainv[(size_t)i * 256 + r * 16 + cc] = Mm[r][cc + 16];
}

// ---------------- sigma init / update ----------------
__global__ void k_initsig(const float* __restrict__ sigma) {
    int i = blockIdx.x * 256 + threadIdx.x;
    g_sig[i] = sigma[0];
}
__global__ void k_sig(int mode) {
    int i = blockIdx.x * 256 + threadIdx.x;
    float ssq, cnt;
    if (mode == 0) {
        ssq = 0.f; 
        #pragma unroll
        for (int sp = 0; sp < SPL; sp++) ssq += g_ssqpart[sp * MS + i];
        cnt = g_cntc[i];
    } else {
        ssq = g_ssq[i];
        cnt = g_cntr[i];
    }
    float alpha = g_coef[3], ll = g_coef[1];
    float tau = sqrtf(ssq) / sqrtf(2.f * cnt * alpha);
    g_sig[i] = tau * ll;
}

// ---------------- B[i] += mu * Ainv[i] @ t[i] ----------------
__global__ void k_upd(int mode) {
    int tid = blockIdx.x * 256 + threadIdx.x;      // 65536
    int i = tid >> 4, r = tid & 15;
    float ml = g_coef[2];
    const float* Ai = g_Ainv + (size_t)i * 256 + r * 16;
    const float* ti = g_t + i * RD;
    float delta = 0.f;
    #pragma unroll
    for (int s = 0; s < RD; s++) delta += Ai[s] * ti[s];
    float* B = mode ? g_U : g_Vt;
    B[tid] += ml * delta;
}

// ---------------- final out = U @ V ----------------
__global__ void k_out(float* __restrict__ out) {
    __shared__ float sU[64 * RD];
    int tx = threadIdx.x;
    int n = blockIdx.x * 256 + tx;
    int m0 = blockIdx.y * 64;
    #pragma unroll
    for (int k = 0; k < 4; k++)
        sU[tx + k * 256] = g_U[m0 * RD + tx + k * 256];
    float v[RD];
    #pragma unroll
    for (int r = 0; r < RD; r++) v[r] = g_Vt[n * RD + r];
    __syncthreads();
    for (int j = 0; j < 64; j++) {
        float dot = 0.f;
        #pragma unroll
        for (int r = 0; r < RD; r++) dot += sU[j * RD + r] * v[r];
        out[(size_t)(m0 + j) * MS + n] = dot;
    }
}

// ---------------- orchestration ----------------
extern "C" void kernel_launch(void* const* d_in, const int* in_sizes, int n_in,
                              void* d_out, int out_size) {
    const float* U_in  = (const float*)d_in[0];
    const float* V_in  = (const float*)d_in[1];
    const float* X     = (const float*)d_in[2];
    const float* c_in  = (const float*)d_in[3];
    const float* l_in  = (const float*)d_in[4];
    const float* m_in  = (const float*)d_in[5];
    const float* sg_in = (const float*)d_in[6];
    float* out = (float*)d_out;

    dim3 gcol(16, SPL), b256(256);

    k_setup<<<256, 256>>>(U_in, V_in);
    k_cnt_col<<<gcol, b256>>>(X);
    k_cnt_fin<<<16, 256>>>();
    k_cnt_row<<<512, 256>>>(X);

    for (int layer = 0; layer < 3; layer++) {
        k_coef<<<1, 32>>>(c_in, l_in, m_in, layer);

        // ---- V step (col-mode) ----
        k_A_col<<<gcol, b256>>>(X);
        k_inv<<<4096, 256>>>(0);
        k_initsig<<<16, 256>>>(sg_in);
        for (int it = 0; it < 2; it++) {
            k_res_col<<<gcol, b256>>>(X);
            k_sig<<<16, 256>>>(0);
            k_t_col<<<gcol, b256>>>(X);
            k_redt<<<256, 256>>>();
            k_upd<<<256, 256>>>(0);
        }

        // ---- U step (row-mode) ----
        k_A_row<<<512, 256>>>(X);
        k_inv<<<4096, 256>>>(1);
        k_initsig<<<16, 256>>>(sg_in);
        for (int it = 0; it < 2; it++) {
            k_res_row<<<512, 256>>>(X);
            k_sig<<<16, 256>>>(1);
            k_t_row<<<512, 256>>>(X);
            k_upd<<<256, 256>>>(1);
        }
    }

    k_out<<<dim3(16, 64), 256>>>(out);
}

// round 4
// speedup vs baseline: 1.1917x; 1.1917x over previous
#include <cuda_runtime.h>
#include <math.h>
#include <stdint.h>

#define MS 4096            // square: M == N == 4096
#define RD 16
#define NP 136             // 16*17/2 symmetric pairs
#define KSPLIT 4           // split-K for gram
#define SPL 8              // split factor for col-mode res/t partials
#define TS 512
#define EPSR 1e-5f
#define AST 36             // smem row stride (floats) for mma tiles

// ---------------- scratch (~20 MB of device globals) ----------------
__device__ float g_Apart[(size_t)KSPLIT * NP * MS];  // 8.9 MB gram partials
__device__ float g_Ainv[(size_t)MS * RD * RD];       // 4.0 MB
__device__ float g_Pt[(size_t)NP * MS];              // 2.2 MB  P transposed [p][s] (tf32 values)
__device__ float g_U[MS * RD];
__device__ float g_Vt[MS * RD];                      // V transposed: [n][r]
__device__ float g_t[MS * RD];
__device__ float g_tpart[(size_t)SPL * MS * RD];
__device__ float g_ssq[MS];
__device__ float g_ssqpart[SPL * MS];
__device__ float g_cntpart[SPL * MS];
__device__ float g_cntc[MS];
__device__ float g_cntr[MS];
__device__ float g_sig[MS];
__device__ float g_coef[4];                          // c, lamda, mu, alpha

// ---------------- setup: copy U, transpose V ----------------
__global__ void k_setup(const float* __restrict__ U, const float* __restrict__ V) {
    int tid = blockIdx.x * 256 + threadIdx.x;
    g_U[tid] = U[tid];
    int n = tid >> 4, r = tid & 15;
    g_Vt[tid] = V[r * MS + n];
}

// ---------------- counts ----------------
__global__ void k_cnt_col(const float* __restrict__ X) {
    int j = blockIdx.x * 256 + threadIdx.x;
    int s0 = blockIdx.y * TS;
    float c = 0.f;
    for (int s = 0; s < TS; s++)
        c += (X[(size_t)(s0 + s) * MS + j] != 0.f) ? 1.f : 0.f;
    g_cntpart[blockIdx.y * MS + j] = c;
}
__global__ void k_cnt_fin() {
    int j = blockIdx.x * 256 + threadIdx.x;
    float c = 0.f;
    #pragma unroll
    for (int sp = 0; sp < SPL; sp++) c += g_cntpart[sp * MS + j];
    g_cntc[j] = c;
}
__global__ void k_cnt_row(const float* __restrict__ X) {
    int wid = threadIdx.x >> 5, lane = threadIdx.x & 31;
    int i = blockIdx.x * 8 + wid;
    float c = 0.f;
    for (int s = lane; s < MS; s += 32)
        c += (X[(size_t)i * MS + s] != 0.f) ? 1.f : 0.f;
    #pragma unroll
    for (int off = 16; off; off >>= 1) c += __shfl_xor_sync(~0u, c, off);
    if (lane == 0) g_cntr[i] = c;
}

// ---------------- per-layer coefficients ----------------
__global__ void k_coef(const float* __restrict__ c, const float* __restrict__ lam,
                       const float* __restrict__ mu, int layer) {
    if (threadIdx.x == 0) {
        double cl = (double)c[layer];
        double chi1 = erf(sqrt(cl));
        double y = 0.5 * cl * cl;
        double chi3 = erf(sqrt(y)) - 2.0 * sqrt(y) * exp(-y) / sqrt(3.14159265358979323846);
        double alpha = cl * (1.0 - chi1) + 0.5 * chi3;
        g_coef[0] = (float)cl;
        g_coef[1] = lam[layer];
        g_coef[2] = mu[layer];
        g_coef[3] = (float)alpha;
    }
}

// ---------------- P build: g_Pt[p][s] = tf32(F[s][r]*F[s][c]) ----------------
__global__ void k_P(int mode) {
    int s = blockIdx.x * 256 + threadIdx.x;
    const float* F = mode ? g_Vt : g_U;
    float u[RD];
    const float4* f4 = (const float4*)(F + s * RD);
    #pragma unroll
    for (int q = 0; q < 4; q++) {
        float4 v = f4[q];
        u[q * 4 + 0] = v.x; u[q * 4 + 1] = v.y; u[q * 4 + 2] = v.z; u[q * 4 + 3] = v.w;
    }
    #pragma unroll
    for (int r = 0; r < RD; r++) {
        #pragma unroll
        for (int cc = 0; cc <= r; cc++) {
            float v = u[r] * u[cc];
            uint32_t t;
            asm("cvt.rna.tf32.f32 %0, %1;" : "=r"(t) : "f"(v));
            g_Pt[(size_t)(r * (r + 1) / 2 + cc) * MS + s] = __uint_as_float(t);
        }
    }
}

// ---------------- tf32 mma.sync Gram: C[j,p] = sum_s mask(X)*Pt[p,s] ----------------
// A = mask tile [128 items x 32 k], B = Pt tile [136 p x 32 k], both K-major, stride AST.
// Warp layout: 4 warps in M (32 rows each = 2 m-tiles), 2 groups in N (9/8 n-tiles).
__device__ __forceinline__ void mma_tf32(float* c, const uint32_t* a, uint32_t b0, uint32_t b1) {
    asm volatile(
        "mma.sync.aligned.m16n8k8.row.col.f32.tf32.tf32.f32 "
        "{%0,%1,%2,%3}, {%4,%5,%6,%7}, {%8,%9}, {%0,%1,%2,%3};"
        : "+f"(c[0]), "+f"(c[1]), "+f"(c[2]), "+f"(c[3])
        : "r"(a[0]), "r"(a[1]), "r"(a[2]), "r"(a[3]), "r"(b0), "r"(b1));
}

__global__ __launch_bounds__(256, 2) void k_gram(const float* __restrict__ X, int mode) {
    __shared__ float As[128 * AST];
    __shared__ float Bs[NP * AST];
    int tx = threadIdx.x, wid = tx >> 5, lane = tx & 31;
    int g = lane >> 2, tig = lane & 3;
    int wm = wid & 3, wn = wid >> 2;
    int j0 = blockIdx.x * 128;
    int sbase = blockIdx.y * (MS / KSPLIT);
    int nbase = wn * 9;                 // group0: n-tiles 0..8, group1: 9..16
    int ntiles = wn ? 8 : 9;

    float c[2][9][4];
    #pragma unroll
    for (int tm = 0; tm < 2; tm++)
        #pragma unroll
        for (int nt = 0; nt < 9; nt++)
            #pragma unroll
            for (int q = 0; q < 4; q++) c[tm][nt][q] = 0.f;

    for (int ch = 0; ch < (MS / KSPLIT) / 32; ch++) {
        int s0 = sbase + ch * 32;
        __syncthreads();
        if (mode == 0) {
            // col-mode: A[jj][s] = mask(X[s0+s, j0+jj]) — transposed staging write
            #pragma unroll
            for (int k = 0; k < 16; k++) {
                int e = tx + k * 256; int jj = e & 127, s = e >> 7;
                float x = X[(size_t)(s0 + s) * MS + j0 + jj];
                As[jj * AST + s] = (x != 0.f) ? 1.f : 0.f;
            }
        } else {
            // row-mode: A[ii][s] = mask(X[j0+ii, s0+s]) — direct
            #pragma unroll
            for (int k = 0; k < 16; k++) {
                int e = tx + k * 256; int ii = e >> 5, s = e & 31;
                float x = X[(size_t)(j0 + ii) * MS + s0 + s];
                As[ii * AST + s] = (x != 0.f) ? 1.f : 0.f;
            }
        }
        #pragma unroll
        for (int k = 0; k < 17; k++) {
            int e = tx + k * 256; int p = e >> 5, s = e & 31;
            Bs[p * AST + s] = g_Pt[(size_t)p * MS + s0 + s];
        }
        __syncthreads();

        #pragma unroll
        for (int t = 0; t < 4; t++) {
            int kc = t * 8;
            uint32_t a[2][4];
            #pragma unroll
            for (int tm = 0; tm < 2; tm++) {
                int r0 = wm * 32 + tm * 16;
                a[tm][0] = __float_as_uint(As[(r0 + g) * AST + kc + tig]);
                a[tm][1] = __float_as_uint(As[(r0 + g + 8) * AST + kc + tig]);
                a[tm][2] = __float_as_uint(As[(r0 + g) * AST + kc + tig + 4]);
                a[tm][3] = __float_as_uint(As[(r0 + g + 8) * AST + kc + tig + 4]);
            }
            #pragma unroll
            for (int nt = 0; nt < 9; nt++) {
                if (nt < ntiles) {
                    int n0 = (nbase + nt) * 8;
                    uint32_t b0 = __float_as_uint(Bs[(n0 + g) * AST + kc + tig]);
                    uint32_t b1 = __float_as_uint(Bs[(n0 + g) * AST + kc + tig + 4]);
                    mma_tf32(c[0][nt], a[0], b0, b1);
                    mma_tf32(c[1][nt], a[1], b0, b1);
                }
            }
        }
    }

    size_t base = (size_t)blockIdx.y * NP * MS;
    #pragma unroll
    for (int tm = 0; tm < 2; tm++) {
        int row = j0 + wm * 32 + tm * 16 + g;
        #pragma unroll
        for (int nt = 0; nt < 9; nt++) {
            if (nt < ntiles) {
                int p0 = (nbase + nt) * 8 + 2 * tig;
                g_Apart[base + (size_t)p0 * MS + row]           = c[tm][nt][0];
                g_Apart[base + (size_t)(p0 + 1) * MS + row]     = c[tm][nt][1];
                g_Apart[base + (size_t)p0 * MS + row + 8]       = c[tm][nt][2];
                g_Apart[base + (size_t)(p0 + 1) * MS + row + 8] = c[tm][nt][3];
            }
        }
    }
}

// ---------------- reduce partials + ridge, invert 16x16; also init sigma ----------------
__global__ void k_inv(const float* __restrict__ sigma) {
    __shared__ float Mm[16][33];
    int t = threadIdx.x;
    int r = t >> 4, cc = t & 15;
    int i = blockIdx.x;
    if (t == 0) g_sig[i] = sigma[0];

    int rr = max(r, cc), cs = min(r, cc);
    int p = rr * (rr + 1) / 2 + cs;
    float sum = 0.f;
    #pragma unroll
    for (int sp = 0; sp < KSPLIT; sp++)
        sum += g_Apart[(size_t)sp * NP * MS + (size_t)p * MS + i];
    if (r == cc) sum += EPSR;
    Mm[r][cc] = sum;
    Mm[r][cc + 16] = (r == cc) ? 1.f : 0.f;
    __syncthreads();

    for (int k = 0; k < 16; k++) {
        float piv = Mm[k][k];
        __syncthreads();
        if (r == k) {
            float pivinv = 1.f / piv;
            Mm[k][cc] *= pivinv;
            Mm[k][cc + 16] *= pivinv;
        }
        __syncthreads();
        float f = Mm[r][k];
        float mk1 = Mm[k][cc];
        float mk2 = Mm[k][cc + 16];
        __syncthreads();
        if (r != k) {
            Mm[r][cc] -= f * mk1;
            Mm[r][cc + 16] -= f * mk2;
        }
        __syncthreads();
    }
    g_Ainv[(size_t)i * 256 + r * 16 + cc] = Mm[r][cc + 16];
}

// ================= col-mode res/t (items = columns of X) =================
__global__ __launch_bounds__(256) void k_res_col(const float* __restrict__ X) {
    __shared__ float sF[TS * RD];
    int tx = threadIdx.x;
    int j = blockIdx.x * 256 + tx;
    int s0 = blockIdx.y * TS;
    #pragma unroll
    for (int k = 0; k < 32; k++)
        sF[tx + k * 256] = g_U[s0 * RD + tx + k * 256];
    float b[RD];
    #pragma unroll
    for (int r = 0; r < RD; r++) b[r] = g_Vt[j * RD + r];
    float cl = g_coef[0];
    float inv_sig = 1.f / g_sig[j];
    __syncthreads();

    float acc = 0.f;
    for (int s = 0; s < TS; s++) {
        float d = X[(size_t)(s0 + s) * MS + j];
        float dot = 0.f;
        #pragma unroll
        for (int r = 0; r < RD; r++) dot += sF[s * RD + r] * b[r];
        float rv = (d != 0.f) ? (d - dot) : 0.f;
        float ps = fminf(fmaxf(rv * inv_sig, -cl), cl);
        acc += ps * ps;
    }
    g_ssqpart[blockIdx.y * MS + j] = acc;
}

__global__ __launch_bounds__(256) void k_t_col(const float* __restrict__ X) {
    __shared__ float sF[TS * RD];
    int tx = threadIdx.x;
    int j = blockIdx.x * 256 + tx;
    int s0 = blockIdx.y * TS;
    #pragma unroll
    for (int k = 0; k < 32; k++)
        sF[tx + k * 256] = g_U[s0 * RD + tx + k * 256];
    float b[RD];
    #pragma unroll
    for (int r = 0; r < RD; r++) b[r] = g_Vt[j * RD + r];
    float thr = g_coef[0] * g_sig[j];
    __syncthreads();

    float acc[RD];
    #pragma unroll
    for (int r = 0; r < RD; r++) acc[r] = 0.f;
    for (int s = 0; s < TS; s++) {
        float d = X[(size_t)(s0 + s) * MS + j];
        float dot = 0.f;
        #pragma unroll
        for (int r = 0; r < RD; r++) dot += sF[s * RD + r] * b[r];
        float rv = (d != 0.f) ? (d - dot) : 0.f;
        float pc = fminf(fmaxf(rv, -thr), thr);
        #pragma unroll
        for (int r = 0; r < RD; r++) acc[r] += sF[s * RD + r] * pc;
    }
    #pragma unroll
    for (int r = 0; r < RD; r++)
        g_tpart[((size_t)blockIdx.y * MS + j) * RD + r] = acc[r];
}

__global__ void k_redt() {
    int tid = blockIdx.x * 256 + threadIdx.x;
    int i = tid >> 4, r = tid & 15;
    float s = 0.f;
    #pragma unroll
    for (int sp = 0; sp < SPL; sp++)
        s += g_tpart[((size_t)sp * MS + i) * RD + r];
    g_t[tid] = s;
}

// ================= row-mode res/t (items = rows of X) =================
__global__ __launch_bounds__(256) void k_res_row(const float* __restrict__ X) {
    __shared__ float sV[RD * 513];
    int tx = threadIdx.x, wid = tx >> 5, lane = tx & 31;
    int i = blockIdx.x * 8 + wid;
    float b[RD];
    #pragma unroll
    for (int r = 0; r < RD; r++) b[r] = g_U[i * RD + r];
    float cl = g_coef[0];
    float inv_sig = 1.f / g_sig[i];

    float acc = 0.f;
    for (int t = 0; t < 8; t++) {
        __syncthreads();
        #pragma unroll
        for (int k = 0; k < 32; k++) {
            int idx = tx + k * 256;
            int s = idx >> 4, r = idx & 15;
            sV[r * 513 + s] = g_Vt[t * 8192 + idx];
        }
        __syncthreads();
        #pragma unroll 2
        for (int k = 0; k < 16; k++) {
            int s = lane + k * 32;
            float d = X[(size_t)i * MS + t * TS + s];
            float dot = 0.f;
            #pragma unroll
            for (int r = 0; r < RD; r++) dot += sV[r * 513 + s] * b[r];
            float rv = (d != 0.f) ? (d - dot) : 0.f;
            float ps = fminf(fmaxf(rv * inv_sig, -cl), cl);
            acc += ps * ps;
        }
    }
    #pragma unroll
    for (int off = 16; off; off >>= 1) acc += __shfl_xor_sync(~0u, acc, off);
    if (lane == 0) g_ssq[i] = acc;
}

__global__ __launch_bounds__(256) void k_t_row(const float* __restrict__ X) {
    __shared__ float sV[RD * 513];
    int tx = threadIdx.x, wid = tx >> 5, lane = tx & 31;
    int i = blockIdx.x * 8 + wid;
    float b[RD];
    #pragma unroll
    for (int r = 0; r < RD; r++) b[r] = g_U[i * RD + r];
    float thr = g_coef[0] * g_sig[i];

    float acc[RD];
    #pragma unroll
    for (int r = 0; r < RD; r++) acc[r] = 0.f;
    for (int t = 0; t < 8; t++) {
        __syncthreads();
        #pragma unroll
        for (int k = 0; k < 32; k++) {
            int idx = tx + k * 256;
            int s = idx >> 4, r = idx & 15;
            sV[r * 513 + s] = g_Vt[t * 8192 + idx];
        }
        __syncthreads();
        #pragma unroll 2
        for (int k = 0; k < 16; k++) {
            int s = lane + k * 32;
            float d = X[(size_t)i * MS + t * TS + s];
            float dot = 0.f;
            #pragma unroll
            for (int r = 0; r < RD; r++) dot += sV[r * 513 + s] * b[r];
            float rv = (d != 0.f) ? (d - dot) : 0.f;
            float pc = fminf(fmaxf(rv, -thr), thr);
            #pragma unroll
            for (int r = 0; r < RD; r++) acc[r] += sV[r * 513 + s] * pc;
        }
    }
    #pragma unroll
    for (int r = 0; r < RD; r++) {
        #pragma unroll
        for (int off = 16; off; off >>= 1)
            acc[r] += __shfl_xor_sync(~0u, acc[r], off);
    }
    if (lane == 0) {
        #pragma unroll
        for (int r = 0; r < RD; r++) g_t[i * RD + r] = acc[r];
    }
}

// ---------------- sigma update ----------------
__global__ void k_sig(int mode) {
    int i = blockIdx.x * 256 + threadIdx.x;
    float ssq, cnt;
    if (mode == 0) {
        ssq = 0.f;
        #pragma unroll
        for (int sp = 0; sp < SPL; sp++) ssq += g_ssqpart[sp * MS + i];
        cnt = g_cntc[i];
    } else {
        ssq = g_ssq[i];
        cnt = g_cntr[i];
    }
    float alpha = g_coef[3], ll = g_coef[1];
    float tau = sqrtf(ssq) / sqrtf(2.f * cnt * alpha);
    g_sig[i] = tau * ll;
}

// ---------------- B[i] += mu * Ainv[i] @ t[i] ----------------
__global__ void k_upd(int mode) {
    int tid = blockIdx.x * 256 + threadIdx.x;
    int i = tid >> 4, r = tid & 15;
    float ml = g_coef[2];
    const float* Ai = g_Ainv + (size_t)i * 256 + r * 16;
    const float* ti = g_t + i * RD;
    float delta = 0.f;
    #pragma unroll
    for (int s = 0; s < RD; s++) delta += Ai[s] * ti[s];
    float* B = mode ? g_U : g_Vt;
    B[tid] += ml * delta;
}

// ---------------- final out = U @ V ----------------
__global__ void k_out(float* __restrict__ out) {
    __shared__ float sU[64 * RD];
    int tx = threadIdx.x;
    int n = blockIdx.x * 256 + tx;
    int m0 = blockIdx.y * 64;
    #pragma unroll
    for (int k = 0; k < 4; k++)
        sU[tx + k * 256] = g_U[m0 * RD + tx + k * 256];
    float v[RD];
    #pragma unroll
    for (int r = 0; r < RD; r++) v[r] = g_Vt[n * RD + r];
    __syncthreads();
    for (int j = 0; j < 64; j++) {
        float dot = 0.f;
        #pragma unroll
        for (int r = 0; r < RD; r++) dot += sU[j * RD + r] * v[r];
        out[(size_t)(m0 + j) * MS + n] = dot;
    }
}

// ---------------- orchestration ----------------
extern "C" void kernel_launch(void* const* d_in, const int* in_sizes, int n_in,
                              void* d_out, int out_size) {
    const float* U_in  = (const float*)d_in[0];
    const float* V_in  = (const float*)d_in[1];
    const float* X     = (const float*)d_in[2];
    const float* c_in  = (const float*)d_in[3];
    const float* l_in  = (const float*)d_in[4];
    const float* m_in  = (const float*)d_in[5];
    const float* sg_in = (const float*)d_in[6];
    float* out = (float*)d_out;

    dim3 gcol(16, SPL), b256(256);
    dim3 ggram(32, KSPLIT);

    k_setup<<<256, 256>>>(U_in, V_in);
    k_cnt_col<<<gcol, b256>>>(X);
    k_cnt_fin<<<16, 256>>>();
    k_cnt_row<<<512, 256>>>(X);

    for (int layer = 0; layer < 3; layer++) {
        k_coef<<<1, 32>>>(c_in, l_in, m_in, layer);

        // ---- V step (col-mode) ----
        k_P<<<16, 256>>>(0);
        k_gram<<<ggram, b256>>>(X, 0);
        k_inv<<<4096, 256>>>(sg_in);
        for (int it = 0; it < 2; it++) {
            k_res_col<<<gcol, b256>>>(X);
            k_sig<<<16, 256>>>(0);
            k_t_col<<<gcol, b256>>>(X);
            k_redt<<<256, 256>>>();
            k_upd<<<256, 256>>>(0);
        }

        // ---- U step (row-mode) ----
        k_P<<<16, 256>>>(1);
        k_gram<<<ggram, b256>>>(X, 1);
        k_inv<<<4096, 256>>>(sg_in);
        for (int it = 0; it < 2; it++) {
            k_res_row<<<512, 256>>>(X);
            k_sig<<<16, 256>>>(1);
            k_t_row<<<512, 256>>>(X);
            k_upd<<<256, 256>>>(1);
        }
    }

    k_out<<<dim3(16, 64), 256>>>(out);
}